// round 5
// baseline (speedup 1.0000x reference)
#include <cuda_runtime.h>

typedef unsigned long long ull;

// ---- SoA weight planes (cos / sin) ----
__device__ __align__(16) float g_w1c[16],   g_w1s[16];     // [co*4 + i*2 + j]
__device__ __align__(16) float g_w2c[544],  g_w2s[544];    // [co*68 + (c*16+i*4+j)]
__device__ __align__(16) float g_wfc[2880], g_wfs[2880];   // [o*288 + f]

__global__ void prep_kernel(const float* __restrict__ w1,
                            const float* __restrict__ w2,
                            const float* __restrict__ wf) {
    int t = threadIdx.x;
    if (t < 16) {
        float s, c; sincosf(w1[t], &s, &c);
        g_w1c[t] = c; g_w1s[t] = s;
    }
    for (int i = t; i < 512; i += blockDim.x) {
        int co = i >> 6, r = i & 63;
        float s, c; sincosf(w2[i], &s, &c);
        g_w2c[co * 68 + r] = c; g_w2s[co * 68 + r] = s;
    }
    for (int i = t; i < 2880; i += blockDim.x) {
        int f = i / 10, o = i % 10;
        float s, c; sincosf(wf[i], &s, &c);
        g_wfc[o * 288 + f] = c; g_wfs[o * 288 + f] = s;
    }
}

// packed dual-FMA: acc(lo,hi) += a(lo,hi) * b(lo,hi)
static __device__ __forceinline__ void ffma2(ull& acc, ull a, ull b) {
    asm("fma.rn.f32x2 %0, %1, %2, %0;" : "+l"(acc) : "l"(a), "l"(b));
}
static __device__ __forceinline__ float f2lo(ull v) { return __uint_as_float((unsigned)v); }
static __device__ __forceinline__ float f2hi(ull v) { return __uint_as_float((unsigned)(v >> 32)); }

// MUFU-free sincos: quadrant reduction + minimax polys (FMA/ALU pipes only)
static __device__ __forceinline__ void fast_sincos(float x, float& s, float& c) {
    float t = fmaf(x, 0.63661977236758134f, 12582912.0f);   // round(x*2/pi) + 1.5*2^23
    unsigned q = __float_as_uint(t);                         // low 2 bits = k mod 4
    float kf = t - 12582912.0f;
    float r = fmaf(kf, -1.57079625129699707031f, x);
    r = fmaf(kf, -7.54978941586159e-08f, r);
    float y = r * r;
    float ps = fmaf(y, -1.95152959e-4f, 8.33216087e-3f);
    ps = fmaf(y, ps, -1.66666546e-1f);
    float s0 = fmaf(r * y, ps, r);
    float pc = fmaf(y, 2.44331571e-5f, -1.38873162e-3f);
    pc = fmaf(y, pc, 4.16666232e-2f);
    pc = fmaf(y, pc, -0.5f);
    float c0 = fmaf(y, pc, 1.0f);
    bool sw = q & 1u;
    float ss = sw ? c0 : s0;
    float cc = sw ? s0 : c0;
    unsigned sgs = (q & 2u) << 30;
    unsigned sgc = ((q + 1u) & 2u) << 30;
    s = __uint_as_float(__float_as_uint(ss) ^ sgs);
    c = __uint_as_float(__float_as_uint(cc) ^ sgc);
}

// MUFU-free rsqrt: bit trick + 2 Newton iterations (~5e-6 rel err)
static __device__ __forceinline__ float fast_rsqrt(float d) {
    float y = __uint_as_float(0x5F3759DFu - (__float_as_uint(d) >> 1));
    float h = 0.5f * d;
    y = y * fmaf(-(h * y), y, 1.5f);
    y = y * fmaf(-(h * y), y, 1.5f);
    return y;
}

__global__ __launch_bounds__(320, 5) void ring_kernel(const float* __restrict__ x,
                                                      float* __restrict__ out) {
    __shared__ __align__(16) float s_pxc[784], s_pxs[784];   // pixel (cos,sin), 28x28
    __shared__ __align__(16) float s_h1c[896], s_h1s[896];   // conv1 out [c*224 + y*16 + x]
    __shared__ __align__(16) float s_h2c[288], s_h2s[288];   // conv2 out [(ho*6+wo)*8 + co]
    __shared__ __align__(16) float s_w1c[16],  s_w1s[16];
    __shared__ __align__(16) float s_w2c[544], s_w2s[544];

    const int tid = threadIdx.x;

    // ---- Stage 0: pixel trig (float4 loads, poly sincos) + weight staging ----
    const float4* xb4 = reinterpret_cast<const float4*>(x + blockIdx.x * 784);
    for (int i = tid; i < 196; i += 320) {
        float4 v = xb4[i];
        float s, c;
        fast_sincos(v.x, s, c); s_pxc[4*i+0] = c; s_pxs[4*i+0] = s;
        fast_sincos(v.y, s, c); s_pxc[4*i+1] = c; s_pxs[4*i+1] = s;
        fast_sincos(v.z, s, c); s_pxc[4*i+2] = c; s_pxs[4*i+2] = s;
        fast_sincos(v.w, s, c); s_pxc[4*i+3] = c; s_pxs[4*i+3] = s;
    }
    if (tid < 16) { s_w1c[tid] = g_w1c[tid]; s_w1s[tid] = g_w1s[tid]; }
    for (int i = tid; i < 544; i += 320) { s_w2c[i] = g_w2c[i]; s_w2s[i] = g_w2s[i]; }
    __syncthreads();

    // ---- Stage 1: conv1 2x2 s2 -> 14x14x4; one spatial pos/thread, 4 co in regs ----
    if (tid < 196) {
        int py = tid / 14, px = tid % 14;
        int base = py * 56 + px * 2;
        ull vc0 = *(const ull*)&s_pxc[base];
        ull vs0 = *(const ull*)&s_pxs[base];
        ull vc1 = *(const ull*)&s_pxc[base + 28];
        ull vs1 = *(const ull*)&s_pxs[base + 28];
        int dst0 = py * 16 + px;
#pragma unroll
        for (int co = 0; co < 4; co++) {
            ulonglong2 wc = *(const ulonglong2*)&s_w1c[co * 4];
            ulonglong2 ws = *(const ulonglong2*)&s_w1s[co * 4];
            ull S = 0, T3 = 0, T4 = 0;
            ffma2(S,  vc0, wc.x); ffma2(S,  vc1, wc.y);
            ffma2(S,  vs0, ws.x); ffma2(S,  vs1, ws.y);
            ffma2(T3, vs0, wc.x); ffma2(T3, vs1, wc.y);
            ffma2(T4, vc0, ws.x); ffma2(T4, vc1, ws.y);
            float Sx = f2lo(S) + f2hi(S);
            float Sy = (f2lo(T3) + f2hi(T3)) - (f2lo(T4) + f2hi(T4));
            float r = fast_rsqrt(fmaxf(Sx * Sx + Sy * Sy, 1e-30f));
            s_h1c[co * 224 + dst0] = Sx * r;
            s_h1s[co * 224 + dst0] = Sy * r;
        }
    }
    __syncthreads();

    // ---- Stage 2: conv2 4x4 s2, 4->8 ch -> 288 outputs; one output/thread ----
    // rotate active window (with wrap) so the idle warp cycles across SMSPs
    int st = tid + ((blockIdx.x & 3) << 5);
    if (st >= 320) st -= 320;
    if (st < 288) {
        int co = st & 7, sp = st >> 3;        // co fastest -> v broadcast in 8-lane groups
        int ho = sp / 6, wo = sp % 6;
        const int vb0 = ho * 32 + wo * 2;
        const int wb0 = co * 68;
        ull S1 = 0, S2 = 0, T3 = 0, T4 = 0;
#pragma unroll
        for (int c = 0; c < 4; c++) {
#pragma unroll
            for (int i = 0; i < 4; i++) {
                int vb = c * 224 + vb0 + i * 16;
                ull vc01 = *(const ull*)&s_h1c[vb];
                ull vc23 = *(const ull*)&s_h1c[vb + 2];
                ull vs01 = *(const ull*)&s_h1s[vb];
                ull vs23 = *(const ull*)&s_h1s[vb + 2];
                int wb = wb0 + c * 16 + i * 4;
                ulonglong2 wc = *(const ulonglong2*)&s_w2c[wb];
                ulonglong2 ws = *(const ulonglong2*)&s_w2s[wb];
                ffma2(S1, vc01, wc.x); ffma2(S1, vc23, wc.y);
                ffma2(S2, vs01, ws.x); ffma2(S2, vs23, ws.y);
                ffma2(T3, vs01, wc.x); ffma2(T3, vs23, wc.y);
                ffma2(T4, vc01, ws.x); ffma2(T4, vc23, ws.y);
            }
        }
        float Sx = (f2lo(S1) + f2hi(S1)) + (f2lo(S2) + f2hi(S2));
        float Sy = (f2lo(T3) + f2hi(T3)) - (f2lo(T4) + f2hi(T4));
        float r = fast_rsqrt(fmaxf(Sx * Sx + Sy * Sy, 1e-30f));
        s_h2c[st] = Sx * r; s_h2s[st] = Sy * r;
    }
    __syncthreads();

    // ---- Stage 3: FF ring layer, one warp per class; wf straight from global ----
    int o = tid >> 5, lane = tid & 31;
    const ull* wfc = reinterpret_cast<const ull*>(g_wfc) + o * 144;
    const ull* wfs = reinterpret_cast<const ull*>(g_wfs) + o * 144;
    ull S = 0, T3 = 0, T4 = 0;
    for (int p = lane; p < 144; p += 32) {
        ull vc = *(const ull*)&s_h2c[2 * p];
        ull vs = *(const ull*)&s_h2s[2 * p];
        ull wc = __ldg(wfc + p);
        ull ws = __ldg(wfs + p);
        ffma2(S,  vc, wc); ffma2(S,  vs, ws);
        ffma2(T3, vs, wc); ffma2(T4, vc, ws);
    }
    float Sx = f2lo(S) + f2hi(S);
    float Sy = (f2lo(T3) + f2hi(T3)) - (f2lo(T4) + f2hi(T4));
#pragma unroll
    for (int off = 16; off; off >>= 1) {
        Sx += __shfl_xor_sync(0xffffffff, Sx, off);
        Sy += __shfl_xor_sync(0xffffffff, Sy, off);
    }
    if (lane == 0)
        out[blockIdx.x * 10 + o] = Sy * fast_rsqrt(fmaxf(Sx * Sx + Sy * Sy, 1e-30f));
}

extern "C" void kernel_launch(void* const* d_in, const int* in_sizes, int n_in,
                              void* d_out, int out_size) {
    const float* x  = (const float*)d_in[0];
    const float* w1 = (const float*)d_in[1];
    const float* w2 = (const float*)d_in[2];
    const float* wf = (const float*)d_in[3];
    float* out = (float*)d_out;
    int B = in_sizes[0] / 784;
    prep_kernel<<<1, 512>>>(w1, w2, wf);
    ring_kernel<<<B, 320>>>(x, out);
}